// round 6
// baseline (speedup 1.0000x reference)
#include <cuda_runtime.h>

// SE3TransformerWrapper: B=256, Nr=4000, Nl=48, K=4, d=32, NATTN=1.
// NATTN=1 => h_r/h_l update einsums are dead; outputs depend only on initial
// h_r, h_l. Fully fused single kernel, one CTA per batch:
//   h_l = relu(gather(hs_lig) @ W^T + b)              (smem)
//   e[k,i] = exp(h_r[i]·h_l[k])    (no max-sub: dots ~N(0,16), max ~22, safe)
//   A = e / sum_i e                                   (one block reduction)
//   Yrec = A @ xyz_rec                                (fused, tree reduction)
// R4: static 32KB smem tile (two 256-row half-stages per 512-row iteration)
// instead of 64KB dynamic + cudaFuncSetAttribute — removes the only
// graph-capture-risky API from kernel_launch while keeping coalesced loads
// and 2 CTAs/SM (single wave).

#define NR 4000
#define NL 48
#define KK 4
#define DD 32
#define THREADS 512
#define NWARPS (THREADS / 32)
#define RPT 8                 // 8 tiles of 512 rows; tile 7 partial (416 rows)
#define HROWS 256             // rows per half-stage
#define HF4 (HROWS * 8)       // 2048 float4 = 32KB

__global__ __launch_bounds__(THREADS, 2)
void se3_fused_kernel(const float* __restrict__ hs_rec,
                      const float* __restrict__ hs_lig,
                      const float* __restrict__ xyz_rec,
                      const float* __restrict__ phi_w,
                      const float* __restrict__ phi_b,
                      const int*   __restrict__ label_idx,
                      float* __restrict__ out,
                      int B)
{
    __shared__ float4 tile[HF4];            // 32KB staging (static, no attribute)
    __shared__ float sh_l[KK][DD];          // h_l after linear+relu
    __shared__ float red[NWARPS][KK];       // warp partials (sum)
    __shared__ float bcast[KK];             // block inv-sum
    __shared__ float ywarp[NWARPS][KK * 3]; // Yrec warp partials

    const int b = blockIdx.x;
    const int t = threadIdx.x;
    const int warp = t >> 5;
    const int lane = t & 31;

    // ---- h_l = relu(Linear(gather(hs_lig))) : 128 threads, one (k,e) each ----
    if (t < KK * DD) {
        const int k = t / DD;
        const int e = t % DD;
        const int idx = label_idx[b * KK + k];
        const float* lig = hs_lig + ((long)b * NL + idx) * DD;
        float acc = phi_b[e];
        #pragma unroll
        for (int dd = 0; dd < DD; dd++)
            acc = fmaf(lig[dd], phi_w[e * DD + dd], acc);
        sh_l[k][e] = fmaxf(acc, 0.0f);
    }
    __syncthreads();

    // ---- main loop: stage half-tile (coalesced), dot + exp + sum ----
    float dots[RPT][KK];                    // exp'd dot values
    float sk[KK] = {0.f, 0.f, 0.f, 0.f};

    const float4* rec4 = (const float4*)(hs_rec + (long)b * NR * DD);

    #pragma unroll
    for (int j = 0; j < RPT; j++) {
        #pragma unroll
        for (int h = 0; h < 2; h++) {
            const int base_row = j * THREADS + h * HROWS;
            const int nrows = (NR - base_row >= HROWS) ? HROWS : (NR - base_row);
            const int n_f4 = nrows * 8;

            // coalesced load: 32 consecutive float4 per warp instr (512B)
            #pragma unroll
            for (int i = 0; i < 4; i++) {
                const int m = t + i * THREADS;
                if (m < n_f4) {
                    const int row = m >> 3;
                    const int q = m & 7;
                    tile[(row << 3) + (q ^ (row & 7))] = rec4[((long)base_row << 3) + m];
                }
            }
            __syncthreads();

            // owning threads (t>>8 == h) compute their row's dots
            if ((t >> 8) == h) {
                const int lrow = t & (HROWS - 1);
                if (lrow < nrows) {
                    float d[KK] = {0.f, 0.f, 0.f, 0.f};
                    #pragma unroll
                    for (int q = 0; q < 8; q++) {
                        const float4 v = tile[(lrow << 3) + (q ^ (lrow & 7))];
                        #pragma unroll
                        for (int k = 0; k < KK; k++) {
                            d[k] = fmaf(v.x, sh_l[k][4 * q + 0], d[k]);
                            d[k] = fmaf(v.y, sh_l[k][4 * q + 1], d[k]);
                            d[k] = fmaf(v.z, sh_l[k][4 * q + 2], d[k]);
                            d[k] = fmaf(v.w, sh_l[k][4 * q + 3], d[k]);
                        }
                    }
                    #pragma unroll
                    for (int k = 0; k < KK; k++) {
                        const float e = __expf(d[k]);   // no max-sub (see header)
                        dots[j][k] = e;
                        sk[k] += e;
                    }
                } else {
                    #pragma unroll
                    for (int k = 0; k < KK; k++) dots[j][k] = 0.f;
                }
            }
            __syncthreads();   // tile reused next half
        }
    }

    // ---- block sum reduction ----
    #pragma unroll
    for (int k = 0; k < KK; k++) {
        #pragma unroll
        for (int off = 16; off > 0; off >>= 1)
            sk[k] += __shfl_xor_sync(0xffffffffu, sk[k], off);
    }
    if (lane == 0) {
        #pragma unroll
        for (int k = 0; k < KK; k++) red[warp][k] = sk[k];
    }
    __syncthreads();
    if (t < KK) {
        float s = 0.f;
        #pragma unroll
        for (int w = 0; w < NWARPS; w++) s += red[w][t];
        bcast[t] = 1.0f / s;
    }
    __syncthreads();
    float inv[KK];
    #pragma unroll
    for (int k = 0; k < KK; k++) inv[k] = bcast[k];

    // ---- write A + accumulate Yrec ----
    const long yrec_total = (long)B * KK * 3;       // A region follows Yrec
    float* Aout = out + yrec_total + (long)b * KK * NR;
    const float* xyz = xyz_rec + (long)b * NR * 3;

    float yacc[KK * 3];
    #pragma unroll
    for (int q = 0; q < KK * 3; q++) yacc[q] = 0.f;

    #pragma unroll
    for (int j = 0; j < RPT; j++) {
        const int r = t + j * THREADS;
        const bool live = (j < RPT - 1) || (r < NR);
        if (live) {
            const float x = xyz[r * 3 + 0];
            const float y = xyz[r * 3 + 1];
            const float z = xyz[r * 3 + 2];
            #pragma unroll
            for (int k = 0; k < KK; k++) {
                const float a = dots[j][k] * inv[k];
                Aout[(long)k * NR + r] = a;
                yacc[k * 3 + 0] = fmaf(a, x, yacc[k * 3 + 0]);
                yacc[k * 3 + 1] = fmaf(a, y, yacc[k * 3 + 1]);
                yacc[k * 3 + 2] = fmaf(a, z, yacc[k * 3 + 2]);
            }
        }
    }

    // ---- deterministic Yrec reduction ----
    #pragma unroll
    for (int q = 0; q < KK * 3; q++) {
        #pragma unroll
        for (int off = 16; off > 0; off >>= 1)
            yacc[q] += __shfl_xor_sync(0xffffffffu, yacc[q], off);
    }
    if (lane == 0) {
        #pragma unroll
        for (int q = 0; q < KK * 3; q++) ywarp[warp][q] = yacc[q];
    }
    __syncthreads();
    if (t < KK * 3) {
        float s = 0.f;
        #pragma unroll
        for (int w = 0; w < NWARPS; w++) s += ywarp[w][t];
        out[(long)b * (KK * 3) + t] = s;   // Yrec[b,k,l]
    }
}

extern "C" void kernel_launch(void* const* d_in, const int* in_sizes, int n_in,
                              void* d_out, int out_size) {
    const float* hs_rec   = (const float*)d_in[0];   // [B,4000,32]
    const float* hs_lig   = (const float*)d_in[1];   // [B,48,32]
    const float* xyz_rec  = (const float*)d_in[2];   // [B,4000,3]
    const float* phi_w    = (const float*)d_in[3];   // [32,32]
    const float* phi_b    = (const float*)d_in[4];   // [32]
    // d_in[5], d_in[6]: ascaler1/2 — dead with NATTN=1
    const int*   label_idx = (const int*)d_in[7];    // [B,4]

    const int B = in_sizes[0] / (NR * DD);

    se3_fused_kernel<<<B, THREADS>>>(hs_rec, hs_lig, xyz_rec, phi_w, phi_b,
                                     label_idx, (float*)d_out, B);
}

// round 9
// speedup vs baseline: 1.0434x; 1.0434x over previous
#include <cuda_runtime.h>

// SE3TransformerWrapper: B=256, Nr=4000, Nl=48, K=4, d=32, NATTN=1.
// NATTN=1 => update einsums dead; outputs depend only on initial h_r, h_l.
//   h_l = relu(gather(hs_lig) @ W^T + b)
//   e[k,i] = exp(h_r[i]·h_l[k])   (no max-sub: dots ~N(0,16), max ~22, safe)
//   A = e / sum_i e ;  Yrec = A @ xyz_rec
// R6 design, R7 fix: warp-cooperative rows — 8 lanes per row, one LDG.128
// per warp = 512B contiguous straight into FMAs (no smem staging). Dots
// combined via 7-shuffle reduce-scatter + 64B/warp smem exchange.
// R7 BUGFIX: inner loop must do 8 iterations (8 x 4 rows = 32 rows/group)
// to match the consumer's 32-rows-per-group indexing; R6 did only 4 and
// left rows 16-31 of each group unset (rel_err 0.887).

#define NR 4000
#define NL 48
#define KK 4
#define DD 32
#define THREADS 512
#define NWARPS 16
#define RPW 250          // rows per warp (4000/16)
#define NGROUPS 8        // 8 groups of 32 rows (last has 26 live)

__global__ __launch_bounds__(THREADS, 2)
void se3_fused_kernel(const float* __restrict__ hs_rec,
                      const float* __restrict__ hs_lig,
                      const float* __restrict__ xyz_rec,
                      const float* __restrict__ phi_w,
                      const float* __restrict__ phi_b,
                      const int*   __restrict__ label_idx,
                      float* __restrict__ out,
                      int B)
{
    __shared__ float4 shT[DD];            // transposed h_l: shT[dd] = {k0..k3}
    __shared__ float4 xch[NWARPS][32];    // per-warp dot exchange (8KB)
    __shared__ float red[NWARPS][KK];     // warp partials (sum)
    __shared__ float bcast[KK];           // block inv-sum
    __shared__ float ywarp[NWARPS][KK * 3];

    const int b = blockIdx.x;
    const int t = threadIdx.x;
    const int w = t >> 5;
    const int l = t & 31;

    // ---- h_l = relu(Linear(gather(hs_lig))), stored transposed ----
    if (t < KK * DD) {
        const int k = t / DD;
        const int e = t % DD;
        const int idx = label_idx[b * KK + k];
        const float* lig = hs_lig + ((long)b * NL + idx) * DD;
        float acc = phi_b[e];
        #pragma unroll
        for (int dd = 0; dd < DD; dd++)
            acc = fmaf(lig[dd], phi_w[e * DD + dd], acc);
        ((float*)shT)[e * KK + k] = fmaxf(acc, 0.0f);
    }
    __syncthreads();

    const float4* rec4 = (const float4*)(hs_rec + (long)b * NR * DD);
    const long base = (long)w * RPW;

    const int q  = l & 7;                 // float4-chunk within row
    const int rg = l >> 3;                // row within 4-row instr

    // per-lane slice of h_l^T (16 floats -> regs)
    const float4 w0 = shT[4 * q + 0];
    const float4 w1 = shT[4 * q + 1];
    const float4 w2 = shT[4 * q + 2];
    const float4 w3 = shT[4 * q + 3];

    float dots[NGROUPS][KK];              // exp'd dots for owned rows
    float sk[KK] = {0.f, 0.f, 0.f, 0.f};

    for (int g = 0; g < NGROUPS; g++) {
        #pragma unroll
        for (int i = 0; i < 8; i++) {     // 8 x 4 rows = 32 rows per group
            const int rowLocal = g * 32 + i * 4 + rg;
            float4 v = make_float4(0.f, 0.f, 0.f, 0.f);
            if (rowLocal < RPW)
                v = rec4[(base + rowLocal) * 8 + q];

            // partial dots for this 16B chunk, all K at once
            float d0 = fmaf(v.x, w0.x, fmaf(v.y, w1.x, fmaf(v.z, w2.x, v.w * w3.x)));
            float d1 = fmaf(v.x, w0.y, fmaf(v.y, w1.y, fmaf(v.z, w2.y, v.w * w3.y)));
            float d2 = fmaf(v.x, w0.z, fmaf(v.y, w1.z, fmaf(v.z, w2.z, v.w * w3.z)));
            float d3 = fmaf(v.x, w0.w, fmaf(v.y, w1.w, fmaf(v.z, w2.w, v.w * w3.w)));

            // 7-shuffle reduce-scatter over the 8 lanes of this row
            const float t0 = __shfl_xor_sync(0xffffffffu, d0, 1);
            const float t1 = __shfl_xor_sync(0xffffffffu, d1, 1);
            const float t2 = __shfl_xor_sync(0xffffffffu, d2, 1);
            const float t3 = __shfl_xor_sync(0xffffffffu, d3, 1);
            float a0, a1;
            if (l & 1) { a0 = d2 + t2; a1 = d3 + t3; }
            else       { a0 = d0 + t0; a1 = d1 + t1; }
            const float s0 = __shfl_xor_sync(0xffffffffu, a0, 2);
            const float s1 = __shfl_xor_sync(0xffffffffu, a1, 2);
            const float bb = ((l >> 1) & 1) ? (a1 + s1) : (a0 + s0);
            const float c  = bb + __shfl_xor_sync(0xffffffffu, bb, 4);
            // lane (l&4)==0 holds full dot, k = ((l&1)<<1)|((l>>1)&1)
            if ((l & 4) == 0) {
                const int kk = ((l & 1) << 1) | ((l >> 1) & 1);
                ((float*)&xch[w][i * 4 + rg])[kk] = c;
            }
        }
        __syncwarp();

        // owner lane picks up its row's 4 dots, exponentiates, accumulates
        const int rowLocal = g * 32 + l;
        if (rowLocal < RPW) {
            const float4 dd = xch[w][l];
            const float e0 = __expf(dd.x);
            const float e1 = __expf(dd.y);
            const float e2 = __expf(dd.z);
            const float e3 = __expf(dd.w);
            dots[g][0] = e0; sk[0] += e0;
            dots[g][1] = e1; sk[1] += e1;
            dots[g][2] = e2; sk[2] += e2;
            dots[g][3] = e3; sk[3] += e3;
        } else {
            #pragma unroll
            for (int k = 0; k < KK; k++) dots[g][k] = 0.f;
        }
        __syncwarp();   // xch reused next group
    }

    // ---- block sum reduction ----
    #pragma unroll
    for (int k = 0; k < KK; k++) {
        #pragma unroll
        for (int off = 16; off > 0; off >>= 1)
            sk[k] += __shfl_xor_sync(0xffffffffu, sk[k], off);
    }
    if (l == 0) {
        #pragma unroll
        for (int k = 0; k < KK; k++) red[w][k] = sk[k];
    }
    __syncthreads();
    if (t < KK) {
        float s = 0.f;
        #pragma unroll
        for (int ww = 0; ww < NWARPS; ww++) s += red[ww][t];
        bcast[t] = 1.0f / s;
    }
    __syncthreads();
    float inv[KK];
    #pragma unroll
    for (int k = 0; k < KK; k++) inv[k] = bcast[k];

    // ---- write A + accumulate Yrec ----
    const long yrec_total = (long)B * KK * 3;
    float* Aout = out + yrec_total + (long)b * KK * NR;
    const float* xyz = xyz_rec + (long)b * NR * 3;

    float yacc[KK * 3];
    #pragma unroll
    for (int p = 0; p < KK * 3; p++) yacc[p] = 0.f;

    for (int g = 0; g < NGROUPS; g++) {
        const int rowLocal = g * 32 + l;
        if (rowLocal < RPW) {
            const long row = base + rowLocal;
            const float x = xyz[row * 3 + 0];
            const float y = xyz[row * 3 + 1];
            const float z = xyz[row * 3 + 2];
            #pragma unroll
            for (int k = 0; k < KK; k++) {
                const float a = dots[g][k] * inv[k];
                Aout[(long)k * NR + row] = a;
                yacc[k * 3 + 0] = fmaf(a, x, yacc[k * 3 + 0]);
                yacc[k * 3 + 1] = fmaf(a, y, yacc[k * 3 + 1]);
                yacc[k * 3 + 2] = fmaf(a, z, yacc[k * 3 + 2]);
            }
        }
    }

    // ---- deterministic Yrec reduction ----
    #pragma unroll
    for (int p = 0; p < KK * 3; p++) {
        #pragma unroll
        for (int off = 16; off > 0; off >>= 1)
            yacc[p] += __shfl_xor_sync(0xffffffffu, yacc[p], off);
    }
    if (l == 0) {
        #pragma unroll
        for (int p = 0; p < KK * 3; p++) ywarp[w][p] = yacc[p];
    }
    __syncthreads();
    if (t < KK * 3) {
        float s = 0.f;
        #pragma unroll
        for (int ww = 0; ww < NWARPS; ww++) s += ywarp[ww][t];
        out[(long)b * (KK * 3) + t] = s;   // Yrec[b,k,l]
    }
}

extern "C" void kernel_launch(void* const* d_in, const int* in_sizes, int n_in,
                              void* d_out, int out_size) {
    const float* hs_rec   = (const float*)d_in[0];   // [B,4000,32]
    const float* hs_lig   = (const float*)d_in[1];   // [B,48,32]
    const float* xyz_rec  = (const float*)d_in[2];   // [B,4000,3]
    const float* phi_w    = (const float*)d_in[3];   // [32,32]
    const float* phi_b    = (const float*)d_in[4];   // [32]
    // d_in[5], d_in[6]: ascaler1/2 — dead with NATTN=1
    const int*   label_idx = (const int*)d_in[7];    // [B,4]

    const int B = in_sizes[0] / (NR * DD);

    se3_fused_kernel<<<B, THREADS>>>(hs_rec, hs_lig, xyz_rec, phi_w, phi_b,
                                     label_idx, (float*)d_out, B);
}